// round 16
// baseline (speedup 1.0000x reference)
#include <cuda_runtime.h>
#include <cuda_bf16.h>
#include <mma.h>
using namespace nvcuda;

#define N 2048
#define D 128
#define R 43
#define KSPLIT 16
#define JSPAN (N / KSPLIT)   // 128
#define ITILE 64
#define TP 128               // pairs per logexp tile
#define NT 8                 // tiles per logexp block
#define TFLOAT4 ((TP * R) / 4)  // 1376 float4 per tile

// -------- scratch (device globals: no allocation allowed) --------
__device__ unsigned g_e2[(size_t)N * N];   // packed E: (bf16 hi) | (bf16 lo << 16)
__device__ unsigned g_x2[N * D];           // packed XS = inp*recip, hi/lo bf16 (1 MB)
__device__ float g_head[N];
__device__ float g_tail[N];
__device__ float g_colsum[N];              // softmax denominators (atomic)

__device__ __forceinline__ void cpasync16(void* dst, const void* src) {
    unsigned d = (unsigned)__cvta_generic_to_shared(dst);
    asm volatile("cp.async.cg.shared.global [%0], [%1], 16;" :: "r"(d), "l"(src));
}

// ================= K1: head/tail projections + zero colsum + zero d_out ==========
__global__ void k_headtail(const float* __restrict__ inp,
                           const float* __restrict__ wh, const float* __restrict__ bh,
                           const float* __restrict__ wt, const float* __restrict__ bt,
                           float* __restrict__ out) {
    int gt = blockIdx.x * blockDim.x + threadIdx.x;     // 65536 threads
    ((float4*)out)[gt] = make_float4(0.f, 0.f, 0.f, 0.f);
    if (gt < N) g_colsum[gt] = 0.f;
    int warp = gt >> 5;
    int lane = threadIdx.x & 31;
    float4 x = ((const float4*)inp)[warp * 32 + lane];
    float4 a = ((const float4*)wh)[lane];
    float4 b = ((const float4*)wt)[lane];
    float h = x.x * a.x + x.y * a.y + x.z * a.z + x.w * a.w;
    float t = x.x * b.x + x.y * b.y + x.z * b.z + x.w * b.w;
#pragma unroll
    for (int o = 16; o; o >>= 1) {
        h += __shfl_xor_sync(0xffffffffu, h, o);
        t += __shfl_xor_sync(0xffffffffu, t, o);
    }
    if (lane == 0) {
        g_head[warp] = h + bh[0];
        g_tail[warp] = t + bt[0];
    }
}

// ================= K2: E = exp(logits), cp.async double-buffered pipeline =========
// Each block walks NT=8 consecutive 128-pair tiles with 2 smem buffers: tile t+1's
// LDGSTS stream is in flight while tile t computes -> DRAM stays busy. The mask
// value for tile t+1 is prefetched into a register during tile t (577-cyc MLP-1
// latency otherwise sits inside the compute phase). Warps 0-3 compute r[0,22)
// partials, warps 4-7 r[22,43); halves combine via a 512B smem exchange on the
// barrier that also frees the buffer. LDS banks conflict-free. E written as ONE
// packed STG.32 stream (R13: split 16-bit plane stores cost ~45 us here).
// max|logit| ~ 8 -> exp without the max pass is safe in fp32 (shift-invariant).
__global__ void __launch_bounds__(256) k_logexp(const float* __restrict__ rel,
                                                const float* __restrict__ mask,
                                                const float* __restrict__ wrel,
                                                const float* __restrict__ brel) {
    __shared__ float sw[44];
    __shared__ __align__(16) float sd[2][TP * R];   // 2 x 22 KB
    __shared__ float sred[TP];
    int tid = threadIdx.x;
    if (tid < R) sw[tid] = wrel[tid];

    size_t t0 = (size_t)blockIdx.x * NT;            // first tile of this block
    const float4* base4 = (const float4*)rel;       // tile tt starts at tt*TFLOAT4

#define ISSUE(tt, buf) do {                                                    \
        const float4* _s = base4 + (size_t)(tt) * TFLOAT4;                     \
        _Pragma("unroll")                                                      \
        for (int _u = 0; _u < 6; _u++) {                                       \
            int _k = tid + _u * 256;                                           \
            if (_k < TFLOAT4)                                                  \
                cpasync16(&sd[buf][_k * 4], _s + _k);                          \
        }                                                                      \
    } while (0)

    ISSUE(t0, 0);
    asm volatile("cp.async.commit_group;");
    ISSUE(t0 + 1, 1);
    asm volatile("cp.async.commit_group;");

    int q = tid & (TP - 1);          // pair within tile
    int h = tid >> 7;                // 0: r[0,22)  1: r[22,43)

    float mcur = 0.f;
    if (!h) mcur = __ldcs(mask + t0 * TP + q);      // mask for tile 0

    for (int t = 0; t < NT; t++) {
        int buf = t & 1;
        asm volatile("cp.async.wait_group 1;");
        __syncthreads();                              // buf data visible

        const float* row = &sd[buf][q * R];
        float dot = 0.f;
        if (h) {
#pragma unroll
            for (int r = 22; r < R; r++) dot = fmaf(row[r], sw[r], dot);
            sred[q] = dot;
        } else {
#pragma unroll
            for (int r = 0; r < 22; r++) dot = fmaf(row[r], sw[r], dot);
        }
        __syncthreads();                              // sred ready + buf free

        if (t + 2 < NT) ISSUE(t0 + t + 2, buf);
        asm volatile("cp.async.commit_group;");

        float mnext = 0.f;
        if (!h && t + 1 < NT)                         // prefetch next tile's mask
            mnext = __ldcs(mask + (t0 + t + 1) * TP + q);

        if (!h) {
            size_t p = (t0 + t) * (size_t)TP + q;
            int i = (int)(p >> 11);
            int j = (int)(p & (N - 1));
            float logit = dot + sred[q] + brel[0]
                        + __ldg(g_head + i) + __ldg(g_tail + j) + mcur;
            float e = __expf(logit);
            __nv_bfloat16 hi = __float2bfloat16(e);
            float hif = __bfloat162float(hi);
            __nv_bfloat16 lo = __float2bfloat16(e - hif);
            unsigned pk = (unsigned)__bfloat16_as_ushort(hi)
                        | ((unsigned)__bfloat16_as_ushort(lo) << 16);
            __stcs(g_e2 + p, pk);
            atomicAdd(&g_colsum[j], hif + __bfloat162float(lo));
        }
        mcur = mnext;
    }
#undef ISSUE
}

// ================= K3: XS = inp * (1/colsum), packed bf16 hi/lo ==================
__global__ void k_xsplit(const float* __restrict__ inp) {
    int t = blockIdx.x * 256 + threadIdx.x;       // 65536 threads, 4 elems each
    int j = t >> 5;
    float rc = __fdividef(1.f, g_colsum[j]);
    float4 v = ((const float4*)inp)[t];
    v.x *= rc; v.y *= rc; v.z *= rc; v.w *= rc;
    uint4 o;
    float f, hf;
#define SPLIT(dst, val) \
    f = (val); hf = __bfloat162float(__float2bfloat16(f)); \
    dst = (unsigned)__bfloat16_as_ushort(__float2bfloat16(f)) \
        | ((unsigned)__bfloat16_as_ushort(__float2bfloat16(f - hf)) << 16)
    SPLIT(o.x, v.x); SPLIT(o.y, v.y); SPLIT(o.z, v.z); SPLIT(o.w, v.w);
#undef SPLIT
    ((uint4*)g_x2)[t] = o;
}

// ================= K4: split-K tensor-core GEMM, vector-RED epilogue =============
// (launch index 3 -> profiled)
// Grid (32, 16): mainloop identical to R15 (reg double-buffered, hi/lo bf16,
// hi*hi + hi*lo + lo*hi). Epilogue changed: red.global.add.v4.f32 cuts REDG issue
// lanes 4.2M -> 1.05M (R15 model: scalar spread-REDG at 1.29 cyc/lane ~ 19 us of
// LSU issue was the kernel's real bottleneck).
__global__ void __launch_bounds__(256, 2) k_gemm(float* __restrict__ out) {
    __shared__ __align__(16) __nv_bfloat16 sEhi[ITILE][40];
    __shared__ __align__(16) __nv_bfloat16 sElo[ITILE][40];
    __shared__ __align__(16) __nv_bfloat16 sXhi[32][136];
    __shared__ __align__(16) __nv_bfloat16 sXlo[32][136];
    __shared__ __align__(16) float sOut[8][256];
    int tid = threadIdx.x;
    int i0 = blockIdx.x * ITILE;
    int jbeg = blockIdx.y * JSPAN;
    int lane = tid & 31;
    int w = tid >> 5;
    int wi = w >> 1;
    int wd = w & 1;

    int er0 = tid >> 3, ec0 = (tid & 7) * 4;
    int er1 = (tid + 256) >> 3, ec1 = ec0;
    const uint4* pe0 = (const uint4*)(g_e2 + (size_t)(i0 + er0) * N + jbeg + ec0);
    const uint4* pe1 = (const uint4*)(g_e2 + (size_t)(i0 + er1) * N + jbeg + ec1);

    wmma::fragment<wmma::accumulator, 16, 16, 16, float> acc[4];
#pragma unroll
    for (int dt = 0; dt < 4; dt++) wmma::fill_fragment(acc[dt], 0.f);

    uint4 ue0, ue1, ux[4];
    ue0 = pe0[0];
    ue1 = pe1[0];
#pragma unroll
    for (int m = 0; m < 4; m++) {
        int k = tid + 256 * m;
        int jr = k >> 5, c4 = (k & 31) * 4;
        ux[m] = *(const uint4*)(g_x2 + (jbeg + jr) * D + c4);
    }

    for (int jc = 0; jc < JSPAN; jc += 32) {
        {
            *(uint2*)&sEhi[er0][ec0] = make_uint2(
                (ue0.x & 0xffffu) | (ue0.y << 16), (ue0.z & 0xffffu) | (ue0.w << 16));
            *(uint2*)&sElo[er0][ec0] = make_uint2(
                (ue0.x >> 16) | (ue0.y & 0xffff0000u), (ue0.z >> 16) | (ue0.w & 0xffff0000u));
            *(uint2*)&sEhi[er1][ec1] = make_uint2(
                (ue1.x & 0xffffu) | (ue1.y << 16), (ue1.z & 0xffffu) | (ue1.w << 16));
            *(uint2*)&sElo[er1][ec1] = make_uint2(
                (ue1.x >> 16) | (ue1.y & 0xffff0000u), (ue1.z >> 16) | (ue1.w & 0xffff0000u));
#pragma unroll
            for (int m = 0; m < 4; m++) {
                int k = tid + 256 * m;
                int jr = k >> 5, c4 = (k & 31) * 4;
                *(uint2*)&sXhi[jr][c4] = make_uint2(
                    (ux[m].x & 0xffffu) | (ux[m].y << 16),
                    (ux[m].z & 0xffffu) | (ux[m].w << 16));
                *(uint2*)&sXlo[jr][c4] = make_uint2(
                    (ux[m].x >> 16) | (ux[m].y & 0xffff0000u),
                    (ux[m].z >> 16) | (ux[m].w & 0xffff0000u));
            }
        }
        __syncthreads();

        int jn = jc + 32;
        if (jn < JSPAN) {
            ue0 = pe0[jn / 4];
            ue1 = pe1[jn / 4];
#pragma unroll
            for (int m = 0; m < 4; m++) {
                int k = tid + 256 * m;
                int jr = k >> 5, c4 = (k & 31) * 4;
                ux[m] = *(const uint4*)(g_x2 + (jbeg + jn + jr) * D + c4);
            }
        }

#pragma unroll
        for (int jj = 0; jj < 32; jj += 16) {
            wmma::fragment<wmma::matrix_a, 16, 16, 16, __nv_bfloat16, wmma::row_major> ahi, alo;
            wmma::load_matrix_sync(ahi, &sEhi[wi * 16][jj], 40);
            wmma::load_matrix_sync(alo, &sElo[wi * 16][jj], 40);
#pragma unroll
            for (int dt = 0; dt < 4; dt++) {
                wmma::fragment<wmma::matrix_b, 16, 16, 16, __nv_bfloat16, wmma::row_major> bhi, blo;
                wmma::load_matrix_sync(bhi, &sXhi[jj][wd * 64 + dt * 16], 136);
                wmma::load_matrix_sync(blo, &sXlo[jj][wd * 64 + dt * 16], 136);
                wmma::mma_sync(acc[dt], ahi, bhi, acc[dt]);
                wmma::mma_sync(acc[dt], ahi, blo, acc[dt]);
                wmma::mma_sync(acc[dt], alo, bhi, acc[dt]);
            }
        }
        __syncthreads();
    }

    // epilogue: fragments -> per-warp smem -> red.global.add.v4.f32 into out
    float* dstw = out + (size_t)(i0 + wi * 16) * D + wd * 64;
#pragma unroll
    for (int dt = 0; dt < 4; dt++) {
        wmma::store_matrix_sync(&sOut[w][0], acc[dt], 16, wmma::mem_row_major);
        __syncwarp();
#pragma unroll
        for (int it = 0; it < 2; it++) {
            int rr = (lane >> 2) + it * 8;
            int g = (lane & 3) * 4;
            float4 v = *(const float4*)&sOut[w][rr * 16 + g];
            float* addr = dstw + (size_t)rr * D + dt * 16 + g;   // 16B-aligned
            asm volatile("red.global.add.v4.f32 [%0], {%1, %2, %3, %4};"
                         :: "l"(addr), "f"(v.x), "f"(v.y), "f"(v.z), "f"(v.w)
                         : "memory");
        }
        __syncwarp();
    }
}

// ================= launch =================
extern "C" void kernel_launch(void* const* d_in, const int* in_sizes, int n_in,
                              void* d_out, int out_size) {
    const float* inputs   = (const float*)d_in[0];
    const float* relation = (const float*)d_in[1];
    const float* rel_mask = (const float*)d_in[2];
    const float* w_rel    = (const float*)d_in[3];
    const float* b_rel    = (const float*)d_in[4];
    const float* w_head   = (const float*)d_in[5];
    const float* b_head   = (const float*)d_in[6];
    const float* w_tail   = (const float*)d_in[7];
    const float* b_tail   = (const float*)d_in[8];
    float* out = (float*)d_out;

    k_headtail<<<256, 256>>>(inputs, w_head, b_head, w_tail, b_tail, out);    // idx 0
    k_logexp<<<(N * N) / (TP * NT), 256>>>(relation, rel_mask, w_rel, b_rel); // idx 1
    k_xsplit<<<256, 256>>>(inputs);                                           // idx 2
    k_gemm<<<dim3(N / ITILE, KSPLIT), 256>>>(out);                            // idx 3 (profiled)
}

// round 17
// speedup vs baseline: 1.0026x; 1.0026x over previous
#include <cuda_runtime.h>
#include <cuda_bf16.h>
#include <mma.h>
using namespace nvcuda;

#define N 2048
#define D 128
#define R 43
#define KSPLIT 16
#define JSPAN (N / KSPLIT)   // 128
#define ITILE 64
#define TP 128               // pairs per logexp tile
#define NT 4                 // tiles per logexp block (R16 showed NT=8 regresses)
#define TFLOAT4 ((TP * R) / 4)  // 1376 float4 per tile

// -------- scratch (device globals: no allocation allowed) --------
__device__ unsigned g_e2[(size_t)N * N];   // packed E: (bf16 hi) | (bf16 lo << 16)
__device__ unsigned g_x2[N * D];           // packed XS = inp*recip, hi/lo bf16 (1 MB)
__device__ float g_head[N];
__device__ float g_tail[N];
__device__ float g_colsum[N];              // softmax denominators (atomic)

__device__ __forceinline__ void cpasync16(void* dst, const void* src) {
    unsigned d = (unsigned)__cvta_generic_to_shared(dst);
    asm volatile("cp.async.cg.shared.global [%0], [%1], 16;" :: "r"(d), "l"(src));
}

// ================= K1: head/tail projections + zero colsum + zero d_out ==========
__global__ void k_headtail(const float* __restrict__ inp,
                           const float* __restrict__ wh, const float* __restrict__ bh,
                           const float* __restrict__ wt, const float* __restrict__ bt,
                           float* __restrict__ out) {
    int gt = blockIdx.x * blockDim.x + threadIdx.x;     // 65536 threads
    ((float4*)out)[gt] = make_float4(0.f, 0.f, 0.f, 0.f);
    if (gt < N) g_colsum[gt] = 0.f;
    int warp = gt >> 5;
    int lane = threadIdx.x & 31;
    float4 x = ((const float4*)inp)[warp * 32 + lane];
    float4 a = ((const float4*)wh)[lane];
    float4 b = ((const float4*)wt)[lane];
    float h = x.x * a.x + x.y * a.y + x.z * a.z + x.w * a.w;
    float t = x.x * b.x + x.y * b.y + x.z * b.z + x.w * b.w;
#pragma unroll
    for (int o = 16; o; o >>= 1) {
        h += __shfl_xor_sync(0xffffffffu, h, o);
        t += __shfl_xor_sync(0xffffffffu, t, o);
    }
    if (lane == 0) {
        g_head[warp] = h + bh[0];
        g_tail[warp] = t + bt[0];
    }
}

// ================= K2: E = exp(logits), cp.async double-buffered (R15 version) ====
// Each block walks NT=4 consecutive 128-pair tiles with 2 smem buffers: tile t+1's
// LDGSTS stream is in flight while tile t computes -> DRAM stays busy. Warps 0-3
// compute r[0,22) partials, warps 4-7 r[22,43); halves combine via a 512B smem
// exchange on the barrier that also frees the buffer. LDS banks conflict-free.
// E written as ONE packed STG.32 stream. max|logit| ~ 8 -> no max pass needed.
__global__ void __launch_bounds__(256) k_logexp(const float* __restrict__ rel,
                                                const float* __restrict__ mask,
                                                const float* __restrict__ wrel,
                                                const float* __restrict__ brel) {
    __shared__ float sw[44];
    __shared__ __align__(16) float sd[2][TP * R];   // 2 x 22 KB
    __shared__ float sred[TP];
    int tid = threadIdx.x;
    if (tid < R) sw[tid] = wrel[tid];

    size_t t0 = (size_t)blockIdx.x * NT;
    const float4* base4 = (const float4*)rel;

#define ISSUE(tt, buf) do {                                                    \
        const float4* _s = base4 + (size_t)(tt) * TFLOAT4;                     \
        _Pragma("unroll")                                                      \
        for (int _u = 0; _u < 6; _u++) {                                       \
            int _k = tid + _u * 256;                                           \
            if (_k < TFLOAT4)                                                  \
                cpasync16(&sd[buf][_k * 4], _s + _k);                          \
        }                                                                      \
    } while (0)

    ISSUE(t0, 0);
    asm volatile("cp.async.commit_group;");
    ISSUE(t0 + 1, 1);
    asm volatile("cp.async.commit_group;");

    int q = tid & (TP - 1);
    int h = tid >> 7;

    for (int t = 0; t < NT; t++) {
        int buf = t & 1;
        asm volatile("cp.async.wait_group 1;");
        __syncthreads();

        const float* row = &sd[buf][q * R];
        float dot = 0.f;
        if (h) {
#pragma unroll
            for (int r = 22; r < R; r++) dot = fmaf(row[r], sw[r], dot);
            sred[q] = dot;
        } else {
#pragma unroll
            for (int r = 0; r < 22; r++) dot = fmaf(row[r], sw[r], dot);
        }
        __syncthreads();

        if (t + 2 < NT) ISSUE(t0 + t + 2, buf);
        asm volatile("cp.async.commit_group;");

        if (!h) {
            size_t p = (t0 + t) * (size_t)TP + q;
            int i = (int)(p >> 11);
            int j = (int)(p & (N - 1));
            float logit = dot + sred[q] + brel[0]
                        + __ldg(g_head + i) + __ldg(g_tail + j) + __ldcs(mask + p);
            float e = __expf(logit);
            __nv_bfloat16 hi = __float2bfloat16(e);
            float hif = __bfloat162float(hi);
            __nv_bfloat16 lo = __float2bfloat16(e - hif);
            unsigned pk = (unsigned)__bfloat16_as_ushort(hi)
                        | ((unsigned)__bfloat16_as_ushort(lo) << 16);
            __stcs(g_e2 + p, pk);
            atomicAdd(&g_colsum[j], hif + __bfloat162float(lo));
        }
    }
#undef ISSUE
}

// ================= K3: XS = inp * (1/colsum), packed bf16 hi/lo ==================
__global__ void k_xsplit(const float* __restrict__ inp) {
    int t = blockIdx.x * 256 + threadIdx.x;
    int j = t >> 5;
    float rc = __fdividef(1.f, g_colsum[j]);
    float4 v = ((const float4*)inp)[t];
    v.x *= rc; v.y *= rc; v.z *= rc; v.w *= rc;
    uint4 o;
    float f, hf;
#define SPLIT(dst, val) \
    f = (val); hf = __bfloat162float(__float2bfloat16(f)); \
    dst = (unsigned)__bfloat16_as_ushort(__float2bfloat16(f)) \
        | ((unsigned)__bfloat16_as_ushort(__float2bfloat16(f - hf)) << 16)
    SPLIT(o.x, v.x); SPLIT(o.y, v.y); SPLIT(o.z, v.z); SPLIT(o.w, v.w);
#undef SPLIT
    ((uint4*)g_x2)[t] = o;
}

// ================= K4: split-K tensor GEMM, 512 threads, v4-RED epilogue =========
// (launch index 3 -> profiled)
// R16 diagnosis: 2 blocks/SM x 8 warps = 16 warps/SM, latency-bound, no pipe >52%.
// Now 512 threads, 16 warps in 4i x 4d (warp tile 16i x 32d, acc[2]=16 regs,
// prefetch 3 uint4 = 12 regs), __launch_bounds__(512,2) caps 64 regs
// -> 2 blocks x 16 warps = 32 warps/SM. Same block tile (64i x 128d x 128j),
// same smem traffic. Epilogue aliases staging smem; red.global.add.v4.f32.
#define SME_HI 0                    // bf16 offsets into carved smem
#define SME_LO (64 * 40)
#define SMX_HI (2 * 64 * 40)
#define SMX_LO (2 * 64 * 40 + 32 * 136)
#define SMEM_HALVES (2 * 64 * 40 + 2 * 32 * 136)   // 13824 bf16 = 27648 B

__global__ void __launch_bounds__(512, 2) k_gemm(float* __restrict__ out) {
    __shared__ __align__(16) __nv_bfloat16 smem[SMEM_HALVES];
    __nv_bfloat16* sEhi = smem + SME_HI;
    __nv_bfloat16* sElo = smem + SME_LO;
    __nv_bfloat16* sXhi = smem + SMX_HI;
    __nv_bfloat16* sXlo = smem + SMX_LO;
    int tid = threadIdx.x;
    int i0 = blockIdx.x * ITILE;
    int jbeg = blockIdx.y * JSPAN;
    int lane = tid & 31;
    int w = tid >> 5;                 // 0..15
    int wi = w >> 2;                  // 0..3 -> i offset 16*wi
    int wd = w & 3;                   // 0..3 -> d offset 32*wd

    // staging coords: E one uint4/thread, X two uint4/thread
    int er = tid >> 3, ec = (tid & 7) * 4;
    const uint4* pe = (const uint4*)(g_e2 + (size_t)(i0 + er) * N + jbeg + ec);

    wmma::fragment<wmma::accumulator, 16, 16, 16, float> acc[2];
    wmma::fill_fragment(acc[0], 0.f);
    wmma::fill_fragment(acc[1], 0.f);

    uint4 ue, ux[2];
    ue = pe[0];
#pragma unroll
    for (int m = 0; m < 2; m++) {
        int k = tid + 512 * m;
        int jr = k >> 5, c4 = (k & 31) * 4;
        ux[m] = *(const uint4*)(g_x2 + (jbeg + jr) * D + c4);
    }

    for (int jc = 0; jc < JSPAN; jc += 32) {
        // unpack current regs -> smem
        *(uint2*)&sEhi[er * 40 + ec] = make_uint2(
            (ue.x & 0xffffu) | (ue.y << 16), (ue.z & 0xffffu) | (ue.w << 16));
        *(uint2*)&sElo[er * 40 + ec] = make_uint2(
            (ue.x >> 16) | (ue.y & 0xffff0000u), (ue.z >> 16) | (ue.w & 0xffff0000u));
#pragma unroll
        for (int m = 0; m < 2; m++) {
            int k = tid + 512 * m;
            int jr = k >> 5, c4 = (k & 31) * 4;
            *(uint2*)&sXhi[jr * 136 + c4] = make_uint2(
                (ux[m].x & 0xffffu) | (ux[m].y << 16),
                (ux[m].z & 0xffffu) | (ux[m].w << 16));
            *(uint2*)&sXlo[jr * 136 + c4] = make_uint2(
                (ux[m].x >> 16) | (ux[m].y & 0xffff0000u),
                (ux[m].z >> 16) | (ux[m].w & 0xffff0000u));
        }
        __syncthreads();

        // prefetch next chunk
        int jn = jc + 32;
        if (jn < JSPAN) {
            ue = pe[jn / 4];
#pragma unroll
            for (int m = 0; m < 2; m++) {
                int k = tid + 512 * m;
                int jr = k >> 5, c4 = (k & 31) * 4;
                ux[m] = *(const uint4*)(g_x2 + (jbeg + jn + jr) * D + c4);
            }
        }

#pragma unroll
        for (int jj = 0; jj < 32; jj += 16) {
            wmma::fragment<wmma::matrix_a, 16, 16, 16, __nv_bfloat16, wmma::row_major> ahi, alo;
            wmma::load_matrix_sync(ahi, &sEhi[wi * 16 * 40 + jj], 40);
            wmma::load_matrix_sync(alo, &sElo[wi * 16 * 40 + jj], 40);
#pragma unroll
            for (int dt = 0; dt < 2; dt++) {
                wmma::fragment<wmma::matrix_b, 16, 16, 16, __nv_bfloat16, wmma::row_major> bhi, blo;
                wmma::load_matrix_sync(bhi, &sXhi[jj * 136 + wd * 32 + dt * 16], 136);
                wmma::load_matrix_sync(blo, &sXlo[jj * 136 + wd * 32 + dt * 16], 136);
                wmma::mma_sync(acc[dt], ahi, bhi, acc[dt]);
                wmma::mma_sync(acc[dt], ahi, blo, acc[dt]);
                wmma::mma_sync(acc[dt], alo, bhi, acc[dt]);
            }
        }
        __syncthreads();
    }

    // epilogue: fragments -> per-warp smem (aliases staging) -> v4 RED into out
    // (final loop __syncthreads guarantees all smem reads are done)
    float* sOut = ((float*)smem) + w * 256;
    float* dstw = out + (size_t)(i0 + wi * 16) * D + wd * 32;
#pragma unroll
    for (int dt = 0; dt < 2; dt++) {
        wmma::store_matrix_sync(sOut, acc[dt], 16, wmma::mem_row_major);
        __syncwarp();
#pragma unroll
        for (int it = 0; it < 2; it++) {
            int rr = (lane >> 2) + it * 8;
            int g = (lane & 3) * 4;
            float4 v = *(const float4*)&sOut[rr * 16 + g];
            float* addr = dstw + (size_t)rr * D + dt * 16 + g;   // 16B-aligned
            asm volatile("red.global.add.v4.f32 [%0], {%1, %2, %3, %4};"
                         :: "l"(addr), "f"(v.x), "f"(v.y), "f"(v.z), "f"(v.w)
                         : "memory");
        }
        __syncwarp();
    }
}

// ================= launch =================
extern "C" void kernel_launch(void* const* d_in, const int* in_sizes, int n_in,
                              void* d_out, int out_size) {
    const float* inputs   = (const float*)d_in[0];
    const float* relation = (const float*)d_in[1];
    const float* rel_mask = (const float*)d_in[2];
    const float* w_rel    = (const float*)d_in[3];
    const float* b_rel    = (const float*)d_in[4];
    const float* w_head   = (const float*)d_in[5];
    const float* b_head   = (const float*)d_in[6];
    const float* w_tail   = (const float*)d_in[7];
    const float* b_tail   = (const float*)d_in[8];
    float* out = (float*)d_out;

    k_headtail<<<256, 256>>>(inputs, w_head, b_head, w_tail, b_tail, out);    // idx 0
    k_logexp<<<(N * N) / (TP * NT), 256>>>(relation, rel_mask, w_rel, b_rel); // idx 1
    k_xsplit<<<256, 256>>>(inputs);                                           // idx 2
    k_gemm<<<dim3(N / ITILE, KSPLIT), 512>>>(out);                            // idx 3 (profiled)
}